// round 16
// baseline (speedup 1.0000x reference)
#include <cuda_runtime.h>
#include <cuda_fp16.h>
#include <cstdint>

#define Tt   2048
#define Hd   2048
#define Ee   32
#define DF   1024
#define DS   4096
#define TOPK 6
#define NGROUP 8
#define GSZ  4
#define TKG  4
#define SCALEF 2.5f

// ---------------- static device scratch (no allocations allowed) ----------------
__device__ float g_combine[Tt * Ee];
__device__ int   g_cnt[Ee];
__device__ int   g_off[Ee];
__device__ int   g_tok[Ee * Tt];

__device__ __align__(16) __half g_xh  [(size_t)Tt * Hd];        // x in fp16 (k-major)
__device__ __align__(16) __half g_s1h [(size_t)Tt * DS];        // shared intermediate fp16
__device__ __align__(16) __half g_acth[(size_t)Tt * TOPK * DF]; // routed act fp16

// ---------------- small kernels ----------------
__global__ void zero_cnt_kernel() {
    if (threadIdx.x < Ee) g_cnt[threadIdx.x] = 0;
}
__global__ void offs_kernel() {
    if (threadIdx.x == 0) {
        int r = 0;
        for (int e = 0; e < Ee; e++) { g_off[e] = r; r += g_cnt[e]; }
    }
}

// x fp32 -> fp16 (layout preserved, k-major)
__global__ void cvt_x_kernel(const float* __restrict__ x) {
    int i = blockIdx.x * 256 + threadIdx.x;          // one float4 per thread
    float4 v = ((const float4*)x)[i];
    __half2 h0 = __floats2half2_rn(v.x, v.y);
    __half2 h1 = __floats2half2_rn(v.z, v.w);
    uint2 u;
    u.x = *(uint32_t*)&h0; u.y = *(uint32_t*)&h1;
    ((uint2*)g_xh)[i] = u;
}

// ---------------- router: one block (128 thr) per token (fp32, unchanged) ----------------
__global__ void router_kernel(const float* __restrict__ x,
                              const float* __restrict__ rw,
                              const float* __restrict__ rb) {
    __shared__ __align__(16) float xs[Hd];
    __shared__ float logits[Ee];
    const int t   = blockIdx.x;
    const int tid = threadIdx.x;
    const float* xt = x + (size_t)t * Hd;

    for (int i = tid; i < Hd / 4; i += 128)
        ((float4*)xs)[i] = ((const float4*)xt)[i];
    __syncthreads();

    const int lane = tid & 31, wid = tid >> 5;
    for (int ei = 0; ei < 8; ei++) {
        int e = wid * 8 + ei;
        const float4* wr = (const float4*)(rw + (size_t)e * Hd);
        float s = 0.f;
        for (int i = lane; i < Hd / 4; i += 32) {
            float4 a = ((const float4*)xs)[i];
            float4 b = wr[i];
            s += a.x * b.x + a.y * b.y + a.z * b.z + a.w * b.w;
        }
        #pragma unroll
        for (int o = 16; o; o >>= 1) s += __shfl_xor_sync(0xffffffffu, s, o);
        if (lane == 0) logits[e] = s;
    }
    __syncthreads();

    if (tid < Ee) g_combine[t * Ee + tid] = 0.f;
    __syncthreads();

    if (tid == 0) {
        float sc[Ee], sfc[Ee];
        for (int e = 0; e < Ee; e++) {
            float v = 1.f / (1.f + expf(-logits[e]));
            sc[e]  = v;
            sfc[e] = v + rb[e];
        }
        float gs[NGROUP];
        for (int g = 0; g < NGROUP; g++) {
            float m1 = -1e30f, m2 = -1e30f;
            for (int j = 0; j < GSZ; j++) {
                float v = sfc[g * GSZ + j];
                if (v > m1) { m2 = m1; m1 = v; }
                else if (v > m2) m2 = v;
            }
            gs[g] = m1 + m2;
        }
        bool gsel[NGROUP];
        for (int g = 0; g < NGROUP; g++) gsel[g] = false;
        for (int k = 0; k < TKG; k++) {
            int bi = -1; float bv = -1e30f;
            for (int g = 0; g < NGROUP; g++)
                if (!gsel[g] && gs[g] > bv) { bv = gs[g]; bi = g; }
            gsel[bi] = true;
        }
        float masked[Ee];
        for (int e = 0; e < Ee; e++) masked[e] = gsel[e / GSZ] ? sfc[e] : 0.0f;

        int   idx[TOPK]; float tw[TOPK]; float tsum = 0.f;
        for (int k = 0; k < TOPK; k++) {
            int bi = 0; float bv = -1e30f;
            for (int e = 0; e < Ee; e++)
                if (masked[e] > bv) { bv = masked[e]; bi = e; }
            masked[bi] = -1e30f;
            idx[k] = bi; tw[k] = sc[bi]; tsum += sc[bi];
        }
        float inv = SCALEF / (tsum + 1e-20f);
        for (int k = 0; k < TOPK; k++) {
            int e = idx[k];
            g_combine[t * Ee + e] = tw[k] * inv;
            int slot = atomicAdd(&g_cnt[e], 1);
            g_tok[e * Tt + slot] = t;
        }
    }
}

// ------- fp16 warp-mma GEMM, B kept fp32 in smem (cp.async 3-stage), packed at frag load -------
// block 128x128x32, 4 warps (64x64), m16n8k16
#define BM 128
#define BN 128
#define BK 32           // k per tile
#define STAGES 3
#define NTHR 128
#define RSTR 20                    // u32 per A smem row (16 data + 4 pad)
#define ASTAGE (BM * RSTR)         // u32 per A stage (2560)
#define BSTR32 132                 // floats per B k-row (128 data + 4 pad -> conflict-free)
#define BSTAGE32 (BK * BSTR32)     // floats per B stage (4224)
#define SMEM_U32 (STAGES * (ASTAGE + BSTAGE32))
#define SMEM_BYTES (SMEM_U32 * 4)  // 81408

__device__ __forceinline__ void mma_f16(float (&c)[4], const uint32_t (&a)[4],
                                        const uint32_t (&b)[2]) {
    asm volatile(
        "mma.sync.aligned.m16n8k16.row.col.f32.f16.f16.f32 "
        "{%0,%1,%2,%3}, {%4,%5,%6,%7}, {%8,%9}, {%0,%1,%2,%3};\n"
        : "+f"(c[0]), "+f"(c[1]), "+f"(c[2]), "+f"(c[3])
        : "r"(a[0]), "r"(a[1]), "r"(a[2]), "r"(a[3]), "r"(b[0]), "r"(b[1]));
}

__device__ __forceinline__ void cp16(uint32_t dst, const void* src, bool valid) {
    int sz = valid ? 16 : 0;
    asm volatile("cp.async.cg.shared.global [%0], [%1], 16, %2;\n"
                 :: "r"(dst), "l"(src), "r"(sz));
}
__device__ __forceinline__ void cp_commit() {
    asm volatile("cp.async.commit_group;\n");
}
__device__ __forceinline__ void cp_wait() {
    asm volatile("cp.async.wait_group %0;\n" :: "n"(STAGES - 2));
}

__device__ __forceinline__ void red2(float* p, float v0, float v1) {
    asm volatile("red.global.add.v2.f32 [%0], {%1,%2};\n" :: "l"(p), "f"(v0), "f"(v1));
}

__device__ __forceinline__ uint32_t packh2(float lo, float hi) {
    __half2 h = __floats2half2_rn(lo, hi);
    return *(uint32_t*)&h;
}

// MODE 0: shared up   (A = xh,        B = s_up fp32,   C = g_s1h fp16, relu2)
// MODE 1: shared down (A = g_s1h,     B = s_dn fp32,   C = out fp32)
// MODE 2: moe up      (A = xh gather, B = w_up[e],     C = g_acth fp16, relu2*combine)
// MODE 3: moe down    (A = g_acth,    B = w_dn[e],     C = out, atomic scatter)
template <int MODE>
__global__ __launch_bounds__(NTHR, 2)
void gemm_kernel(float* __restrict__ Cglob, const float* __restrict__ Bglob) {
    extern __shared__ uint32_t smem[];
    uint32_t* As = smem;
    float*    Bs = (float*)(smem + STAGES * ASTAGE);

    constexpr int Kk = (MODE == 1) ? DS : ((MODE == 3) ? DF : Hd);
    constexpr int Nn = (MODE == 0) ? DS : ((MODE == 2) ? DF : Hd);

    const int tid = threadIdx.x;
    const int e  = (MODE >= 2) ? blockIdx.z : 0;
    const int m0 = blockIdx.y * BM;
    const int n0 = blockIdx.x * BN;

    int ne = Tt, off_e = 0;
    const __half* Ah = (MODE == 1) ? g_s1h : ((MODE == 3) ? g_acth : g_xh);
    const float* Bp = Bglob;
    if (MODE >= 2) {
        ne = g_cnt[e];
        if (m0 >= ne) return;
        off_e = g_off[e];
        Bp = Bglob + (size_t)e * Kk * Nn;
    }

    // ---- A loader (cp.async, fp16, 4 x 16B chunks per thread) ----
    const int lr = tid >> 2;            // 0..31
    const int lc = tid & 3;             // chunk within 32-half row
    const __half* aSrc[4];
    #pragma unroll
    for (int i = 0; i < 4; i++) {
        int r = m0 + lr + i * 32;
        int grow;
        if (MODE == 2)      grow = (r < ne) ? g_tok[e * Tt + r] : -1;
        else if (MODE == 3) grow = (r < ne) ? (off_e + r) : -1;
        else                grow = r;
        aSrc[i] = (grow >= 0) ? (Ah + (size_t)grow * Kk + lc * 8) : nullptr;
    }
    const uint32_t aBase = (uint32_t)__cvta_generic_to_shared(As) + ((lr * RSTR + lc * 4) * 4);

    // ---- B loader (cp.async, fp32, 8 x 16B chunks per thread) ----
    // row r = tid>>2 (0..31), chunks c = (tid&3) + 4i (i=0..7), 4 floats each
    const float* bSrc = Bp + (size_t)lr * Nn + n0 + lc * 4;
    const uint32_t bBase = (uint32_t)__cvta_generic_to_shared(Bs) + ((lr * BSTR32 + lc * 4) * 4);

    auto issue = [&](int k0, int st) {   // k0 in k units
        uint32_t ad = aBase + st * (ASTAGE * 4);
        #pragma unroll
        for (int i = 0; i < 4; i++)
            cp16(ad + i * (32 * RSTR * 4),
                 aSrc[i] ? (aSrc[i] + k0) : Ah, aSrc[i] != nullptr);
        uint32_t bd = bBase + st * (BSTAGE32 * 4);
        const float* bp = bSrc + (size_t)k0 * Nn;
        #pragma unroll
        for (int i = 0; i < 8; i++)
            cp16(bd + i * 64, bp + 16 * i, true);
        cp_commit();
    };

    // ---- warp tiling: 2(m) x 2(n) warps, 64x64 per warp ----
    const int lane = tid & 31, wid = tid >> 5;
    const int qr = lane >> 2, qc = lane & 3;
    const int mb = (wid & 1) * 64;
    const int nb = (wid >> 1) * 64;

    float acc[4][8][4];
    #pragma unroll
    for (int mt = 0; mt < 4; mt++)
        #pragma unroll
        for (int nt = 0; nt < 8; nt++)
            #pragma unroll
            for (int j = 0; j < 4; j++) acc[mt][nt][j] = 0.f;

    const int nk = Kk / BK;

    #pragma unroll
    for (int s = 0; s < STAGES - 1; s++) issue(s * BK, s);

    for (int kb = 0; kb < nk; kb++) {
        cp_wait();
        __syncthreads();   // single barrier per K-tile (3-stage rotation)

        if (kb + STAGES - 1 < nk) issue((kb + STAGES - 1) * BK, (kb + STAGES - 1) % STAGES);
        else                      cp_commit();   // keep group counts aligned

        const uint32_t* Au = As + (kb % STAGES) * ASTAGE;
        const float*    Bu = Bs + (kb % STAGES) * BSTAGE32;

        #pragma unroll
        for (int s = 0; s < 2; s++) {        // two k16 steps
            uint32_t afr[4][4], bfr[8][2];
            #pragma unroll
            for (int mt = 0; mt < 4; mt++) {
                int r = mb + mt * 16 + qr;
                afr[mt][0] = Au[r * RSTR + 8 * s + qc];
                afr[mt][1] = Au[(r + 8) * RSTR + 8 * s + qc];
                afr[mt][2] = Au[r * RSTR + 8 * s + qc + 4];
                afr[mt][3] = Au[(r + 8) * RSTR + 8 * s + qc + 4];
            }
            const int k0 = 16 * s + 2 * qc;
            #pragma unroll
            for (int nt = 0; nt < 8; nt++) {
                int n = nb + nt * 8 + qr;
                bfr[nt][0] = packh2(Bu[k0 * BSTR32 + n],       Bu[(k0 + 1) * BSTR32 + n]);
                bfr[nt][1] = packh2(Bu[(k0 + 8) * BSTR32 + n], Bu[(k0 + 9) * BSTR32 + n]);
            }
            #pragma unroll
            for (int mt = 0; mt < 4; mt++)
                #pragma unroll
                for (int nt = 0; nt < 8; nt++)
                    mma_f16(acc[mt][nt], afr[mt], bfr[nt]);
        }
    }

    // -------- epilogue --------
    #pragma unroll
    for (int mt = 0; mt < 4; mt++) {
        int rl0 = mb + mt * 16 + qr;
        int rl1 = rl0 + 8;
        if (MODE == 0) {
            int r0 = m0 + rl0, r1 = m0 + rl1;
            #pragma unroll
            for (int nt = 0; nt < 8; nt++) {
                int c = n0 + nb + nt * 8 + qc * 2;
                float v0 = fmaxf(acc[mt][nt][0], 0.f); v0 *= v0;
                float v1 = fmaxf(acc[mt][nt][1], 0.f); v1 *= v1;
                float v2 = fmaxf(acc[mt][nt][2], 0.f); v2 *= v2;
                float v3 = fmaxf(acc[mt][nt][3], 0.f); v3 *= v3;
                *(__half2*)&g_s1h[(size_t)r0 * Nn + c] = __floats2half2_rn(v0, v1);
                *(__half2*)&g_s1h[(size_t)r1 * Nn + c] = __floats2half2_rn(v2, v3);
            }
        } else if (MODE == 1) {
            int r0 = m0 + rl0, r1 = m0 + rl1;
            #pragma unroll
            for (int nt = 0; nt < 8; nt++) {
                int c = n0 + nb + nt * 8 + qc * 2;
                *(float2*)&Cglob[(size_t)r0 * Nn + c] = make_float2(acc[mt][nt][0], acc[mt][nt][1]);
                *(float2*)&Cglob[(size_t)r1 * Nn + c] = make_float2(acc[mt][nt][2], acc[mt][nt][3]);
            }
        } else if (MODE == 2) {
            bool va = (m0 + rl0) < ne, vb = (m0 + rl1) < ne;
            int tk0 = va ? g_tok[e * Tt + m0 + rl0] : 0;
            int tk1 = vb ? g_tok[e * Tt + m0 + rl1] : 0;
            float w0 = va ? g_combine[tk0 * Ee + e] : 0.f;
            float w1 = vb ? g_combine[tk1 * Ee + e] : 0.f;
            size_t cr0 = (size_t)(off_e + m0 + rl0) * DF;
            size_t cr1 = (size_t)(off_e + m0 + rl1) * DF;
            #pragma unroll
            for (int nt = 0; nt < 8; nt++) {
                int c = n0 + nb + nt * 8 + qc * 2;
                float v0 = fmaxf(acc[mt][nt][0], 0.f); v0 = v0 * v0 * w0;
                float v1 = fmaxf(acc[mt][nt][1], 0.f); v1 = v1 * v1 * w0;
                float v2 = fmaxf(acc[mt][nt][2], 0.f); v2 = v2 * v2 * w1;
                float v3 = fmaxf(acc[mt][nt][3], 0.f); v3 = v3 * v3 * w1;
                if (va) *(__half2*)&g_acth[cr0 + c] = __floats2half2_rn(v0, v1);
                if (vb) *(__half2*)&g_acth[cr1 + c] = __floats2half2_rn(v2, v3);
            }
        } else {  // MODE 3: vector atomic scatter into out
            bool va = (m0 + rl0) < ne, vb = (m0 + rl1) < ne;
            int tk0 = va ? g_tok[e * Tt + m0 + rl0] : 0;
            int tk1 = vb ? g_tok[e * Tt + m0 + rl1] : 0;
            #pragma unroll
            for (int nt = 0; nt < 8; nt++) {
                int c = n0 + nb + nt * 8 + qc * 2;
                if (va) red2(&Cglob[(size_t)tk0 * Hd + c], acc[mt][nt][0], acc[mt][nt][1]);
                if (vb) red2(&Cglob[(size_t)tk1 * Hd + c], acc[mt][nt][2], acc[mt][nt][3]);
            }
        }
    }
}

// ---------------- launch ----------------
extern "C" void kernel_launch(void* const* d_in, const int* in_sizes, int n_in,
                              void* d_out, int out_size) {
    const float* x     = (const float*)d_in[0];
    const float* rw    = (const float*)d_in[1];
    const float* rb    = (const float*)d_in[2];
    const float* w_up  = (const float*)d_in[3];
    const float* w_dn  = (const float*)d_in[4];
    const float* s_up  = (const float*)d_in[5];
    const float* s_dn  = (const float*)d_in[6];
    float* out = (float*)d_out;

    cudaFuncSetAttribute(gemm_kernel<0>, cudaFuncAttributeMaxDynamicSharedMemorySize, SMEM_BYTES);
    cudaFuncSetAttribute(gemm_kernel<1>, cudaFuncAttributeMaxDynamicSharedMemorySize, SMEM_BYTES);
    cudaFuncSetAttribute(gemm_kernel<2>, cudaFuncAttributeMaxDynamicSharedMemorySize, SMEM_BYTES);
    cudaFuncSetAttribute(gemm_kernel<3>, cudaFuncAttributeMaxDynamicSharedMemorySize, SMEM_BYTES);

    // pre-pass: only x -> fp16 (weights read fp32 directly, converted in-loader)
    cvt_x_kernel<<<(Tt * Hd / 4) / 256, 256>>>(x);

    zero_cnt_kernel<<<1, 32>>>();
    router_kernel<<<Tt, 128>>>(x, rw, rb);
    offs_kernel<<<1, 32>>>();

    // routed up: per-expert gathered GEMM -> g_acth
    gemm_kernel<2><<<dim3(DF / BN, Tt / BM, Ee), NTHR, SMEM_BYTES>>>(nullptr, w_up);

    // shared expert
    gemm_kernel<0><<<dim3(DS / BN, Tt / BM, 1), NTHR, SMEM_BYTES>>>(nullptr, s_up);
    gemm_kernel<1><<<dim3(Hd / BN, Tt / BM, 1), NTHR, SMEM_BYTES>>>(out, s_dn);

    // routed down: atomic scatter onto out (after shared wrote it)
    gemm_kernel<3><<<dim3(Hd / BN, Tt / BM, Ee), NTHR, SMEM_BYTES>>>(out, w_dn);
}

// round 17
// speedup vs baseline: 1.2197x; 1.2197x over previous
#include <cuda_runtime.h>
#include <cuda_fp16.h>
#include <cstdint>

#define Tt   2048
#define Hd   2048
#define Ee   32
#define DF   1024
#define DS   4096
#define TOPK 6
#define NGROUP 8
#define GSZ  4
#define TKG  4
#define SCALEF 2.5f

// ---------------- static device scratch (no allocations allowed) ----------------
__device__ float g_combine[Tt * Ee];
__device__ int   g_cnt[Ee];
__device__ int   g_off[Ee];
__device__ int   g_tok[Ee * Tt];

__device__ __align__(16) __half   g_xh  [(size_t)Tt * Hd];        // x fp16 (k-major)
__device__ __align__(16) __half   g_s1h [(size_t)Tt * DS];        // shared intermediate fp16
__device__ __align__(16) __half   g_acth[(size_t)Tt * TOPK * DF]; // routed act fp16
// k-pair-packed fp16 weights: [B][K/2][N] u32, word = {W[2kp][n], W[2kp+1][n]}
__device__ __align__(16) uint32_t g_wupp[(size_t)Ee * (Hd / 2) * DF];
__device__ __align__(16) uint32_t g_wdnp[(size_t)Ee * (DF / 2) * Hd];
__device__ __align__(16) uint32_t g_supp[(size_t)(Hd / 2) * DS];
__device__ __align__(16) uint32_t g_sdnp[(size_t)(DS / 2) * Hd];

// ---------------- small kernels ----------------
__global__ void zero_cnt_kernel() {
    if (threadIdx.x < Ee) g_cnt[threadIdx.x] = 0;
}
__global__ void offs_kernel() {
    if (threadIdx.x == 0) {
        int r = 0;
        for (int e = 0; e < Ee; e++) { g_off[e] = r; r += g_cnt[e]; }
    }
}

__device__ __forceinline__ uint32_t packh2(float lo, float hi) {
    __half2 h = __floats2half2_rn(lo, hi);
    return *(uint32_t*)&h;
}

// x fp32 -> fp16 (layout preserved, k-major)
__global__ void cvt_x_kernel(const float* __restrict__ x) {
    int i = blockIdx.x * 256 + threadIdx.x;          // one float4 per thread
    float4 v = ((const float4*)x)[i];
    uint2 u;
    u.x = packh2(v.x, v.y);
    u.y = packh2(v.z, v.w);
    ((uint2*)g_xh)[i] = u;
}

// W fp32 [B][K][N] -> Wp u32 [B][K/2][N], word = {W[2kp][n], W[2kp+1][n]}.
// Pure streaming: both source rows coalesced float4, dst coalesced uint4.
// shift = log2(N/4). Flattened row index encodes b*(K/2)+kp.
__global__ __launch_bounds__(256)
void pack_kernel(const float* __restrict__ W, uint32_t* __restrict__ Wp,
                 int N, int shift) {
    size_t idx = (size_t)blockIdx.x * 256 + threadIdx.x;
    size_t row = idx >> shift;
    int n4 = (int)(idx & ((1u << shift) - 1));
    const float* r0 = W + row * 2 * (size_t)N + n4 * 4;
    float4 a = *(const float4*)r0;
    float4 c = *(const float4*)(r0 + N);
    uint4 o;
    o.x = packh2(a.x, c.x);
    o.y = packh2(a.y, c.y);
    o.z = packh2(a.z, c.z);
    o.w = packh2(a.w, c.w);
    *(uint4*)(Wp + row * (size_t)N + n4 * 4) = o;
}

// ---------------- router: one block (128 thr) per token (fp32, unchanged) ----------------
__global__ void router_kernel(const float* __restrict__ x,
                              const float* __restrict__ rw,
                              const float* __restrict__ rb) {
    __shared__ __align__(16) float xs[Hd];
    __shared__ float logits[Ee];
    const int t   = blockIdx.x;
    const int tid = threadIdx.x;
    const float* xt = x + (size_t)t * Hd;

    for (int i = tid; i < Hd / 4; i += 128)
        ((float4*)xs)[i] = ((const float4*)xt)[i];
    __syncthreads();

    const int lane = tid & 31, wid = tid >> 5;
    for (int ei = 0; ei < 8; ei++) {
        int e = wid * 8 + ei;
        const float4* wr = (const float4*)(rw + (size_t)e * Hd);
        float s = 0.f;
        for (int i = lane; i < Hd / 4; i += 32) {
            float4 a = ((const float4*)xs)[i];
            float4 b = wr[i];
            s += a.x * b.x + a.y * b.y + a.z * b.z + a.w * b.w;
        }
        #pragma unroll
        for (int o = 16; o; o >>= 1) s += __shfl_xor_sync(0xffffffffu, s, o);
        if (lane == 0) logits[e] = s;
    }
    __syncthreads();

    if (tid < Ee) g_combine[t * Ee + tid] = 0.f;
    __syncthreads();

    if (tid == 0) {
        float sc[Ee], sfc[Ee];
        for (int e = 0; e < Ee; e++) {
            float v = 1.f / (1.f + expf(-logits[e]));
            sc[e]  = v;
            sfc[e] = v + rb[e];
        }
        float gs[NGROUP];
        for (int g = 0; g < NGROUP; g++) {
            float m1 = -1e30f, m2 = -1e30f;
            for (int j = 0; j < GSZ; j++) {
                float v = sfc[g * GSZ + j];
                if (v > m1) { m2 = m1; m1 = v; }
                else if (v > m2) m2 = v;
            }
            gs[g] = m1 + m2;
        }
        bool gsel[NGROUP];
        for (int g = 0; g < NGROUP; g++) gsel[g] = false;
        for (int k = 0; k < TKG; k++) {
            int bi = -1; float bv = -1e30f;
            for (int g = 0; g < NGROUP; g++)
                if (!gsel[g] && gs[g] > bv) { bv = gs[g]; bi = g; }
            gsel[bi] = true;
        }
        float masked[Ee];
        for (int e = 0; e < Ee; e++) masked[e] = gsel[e / GSZ] ? sfc[e] : 0.0f;

        int   idx[TOPK]; float tw[TOPK]; float tsum = 0.f;
        for (int k = 0; k < TOPK; k++) {
            int bi = 0; float bv = -1e30f;
            for (int e = 0; e < Ee; e++)
                if (masked[e] > bv) { bv = masked[e]; bi = e; }
            masked[bi] = -1e30f;
            idx[k] = bi; tw[k] = sc[bi]; tsum += sc[bi];
        }
        float inv = SCALEF / (tsum + 1e-20f);
        for (int k = 0; k < TOPK; k++) {
            int e = idx[k];
            g_combine[t * Ee + e] = tw[k] * inv;
            int slot = atomicAdd(&g_cnt[e], 1);
            g_tok[e * Tt + slot] = t;
        }
    }
}

// ------- fp16 warp-mma GEMM: 128x128x32 block, 4 warps (64x64), m16n8k16, cp.async x3 -------
// A: fp16 k-major rows. B: pre-packed u32 kp-rows [K/2][N].
#define BM 128
#define BN 128
#define BK 32           // k per tile (16 kp)
#define STAGES 3
#define NTHR 128
#define RSTR 20                    // u32 per A smem row (16 data + 4 pad)
#define ASTAGE (BM * RSTR)         // 2560 u32
#define BSTR 136                   // u32 per B kp-row (128 data + 8 pad -> conflict-free)
#define BSTAGE (16 * BSTR)         // 2176 u32
#define SMEM_U32 (STAGES * (ASTAGE + BSTAGE))
#define SMEM_BYTES (SMEM_U32 * 4)  // 56832

__device__ __forceinline__ void mma_f16(float (&c)[4], const uint32_t (&a)[4],
                                        const uint32_t (&b)[2]) {
    asm volatile(
        "mma.sync.aligned.m16n8k16.row.col.f32.f16.f16.f32 "
        "{%0,%1,%2,%3}, {%4,%5,%6,%7}, {%8,%9}, {%0,%1,%2,%3};\n"
        : "+f"(c[0]), "+f"(c[1]), "+f"(c[2]), "+f"(c[3])
        : "r"(a[0]), "r"(a[1]), "r"(a[2]), "r"(a[3]), "r"(b[0]), "r"(b[1]));
}

__device__ __forceinline__ void cp16(uint32_t dst, const void* src, bool valid) {
    int sz = valid ? 16 : 0;
    asm volatile("cp.async.cg.shared.global [%0], [%1], 16, %2;\n"
                 :: "r"(dst), "l"(src), "r"(sz));
}
__device__ __forceinline__ void cp_commit() {
    asm volatile("cp.async.commit_group;\n");
}
__device__ __forceinline__ void cp_wait() {
    asm volatile("cp.async.wait_group %0;\n" :: "n"(STAGES - 2));
}

__device__ __forceinline__ void red2(float* p, float v0, float v1) {
    asm volatile("red.global.add.v2.f32 [%0], {%1,%2};\n" :: "l"(p), "f"(v0), "f"(v1));
}

// MODE 0: shared up   (A = xh,        B = g_supp,    C = g_s1h fp16, relu2)
// MODE 1: shared down (A = g_s1h,     B = g_sdnp,    C = out fp32)
// MODE 2: moe up      (A = xh gather, B = g_wupp[e], C = g_acth fp16, relu2*combine)
// MODE 3: moe down    (A = g_acth,    B = g_wdnp[e], C = out, atomic scatter)
template <int MODE>
__global__ __launch_bounds__(NTHR, 2)
void gemm_kernel(float* __restrict__ Cglob) {
    extern __shared__ uint32_t smem[];
    uint32_t* As = smem;
    uint32_t* Bs = smem + STAGES * ASTAGE;

    constexpr int Kk = (MODE == 1) ? DS : ((MODE == 3) ? DF : Hd);
    constexpr int Nn = (MODE == 0) ? DS : ((MODE == 2) ? DF : Hd);

    const int tid = threadIdx.x;
    const int e  = (MODE >= 2) ? blockIdx.z : 0;
    const int m0 = blockIdx.y * BM;
    const int n0 = blockIdx.x * BN;

    int ne = Tt, off_e = 0;
    const __half* Ah = (MODE == 1) ? g_s1h : ((MODE == 3) ? g_acth : g_xh);
    const uint32_t* Bp;
    if (MODE == 0) Bp = g_supp;
    else if (MODE == 1) Bp = g_sdnp;
    else if (MODE == 2) Bp = g_wupp + (size_t)e * (Kk / 2) * Nn;
    else Bp = g_wdnp + (size_t)e * (Kk / 2) * Nn;

    if (MODE >= 2) {
        ne = g_cnt[e];
        if (m0 >= ne) return;
        off_e = g_off[e];
    }

    // ---- A loader (cp.async, fp16, 4 x 16B chunks per thread) ----
    const int lr = tid >> 2;            // 0..31
    const int lc = tid & 3;             // chunk within 32-half row
    const __half* aSrc[4];
    #pragma unroll
    for (int i = 0; i < 4; i++) {
        int r = m0 + lr + i * 32;
        int grow;
        if (MODE == 2)      grow = (r < ne) ? g_tok[e * Tt + r] : -1;
        else if (MODE == 3) grow = (r < ne) ? (off_e + r) : -1;
        else                grow = r;
        aSrc[i] = (grow >= 0) ? (Ah + (size_t)grow * Kk + lc * 8) : nullptr;
    }
    const uint32_t aBase = (uint32_t)__cvta_generic_to_shared(As) + ((lr * RSTR + lc * 4) * 4);

    // ---- B loader (cp.async of packed u32 kp-rows, 4 x 16B chunks per thread) ----
    // kp-row r = tid>>3 (0..15), u32 col = (tid&7)*4 + 32i (i=0..3)
    const int bkr = tid >> 3;
    const int bc4 = (tid & 7) * 4;
    const uint32_t* bSrc = Bp + (size_t)bkr * Nn + n0 + bc4;
    const uint32_t bBase = (uint32_t)__cvta_generic_to_shared(Bs) + ((bkr * BSTR + bc4) * 4);

    auto issue = [&](int kb, int st) {
        uint32_t ad = aBase + st * (ASTAGE * 4);
        const int k0 = kb * BK;   // halves
        #pragma unroll
        for (int i = 0; i < 4; i++)
            cp16(ad + i * (32 * RSTR * 4),
                 aSrc[i] ? (aSrc[i] + k0) : Ah, aSrc[i] != nullptr);
        uint32_t bd = bBase + st * (BSTAGE * 4);
        const uint32_t* bp = bSrc + (size_t)(kb * 16) * Nn;
        #pragma unroll
        for (int i = 0; i < 4; i++)
            cp16(bd + i * 128, bp + 32 * i, true);
        cp_commit();
    };

    // ---- warp tiling: 2(m) x 2(n) warps, 64x64 per warp ----
    const int lane = tid & 31, wid = tid >> 5;
    const int qr = lane >> 2, qc = lane & 3;
    const int mb = (wid & 1) * 64;
    const int nb = (wid >> 1) * 64;

    float acc[4][8][4];
    #pragma unroll
    for (int mt = 0; mt < 4; mt++)
        #pragma unroll
        for (int nt = 0; nt < 8; nt++)
            #pragma unroll
            for (int j = 0; j < 4; j++) acc[mt][nt][j] = 0.f;

    const int nk = Kk / BK;

    #pragma unroll
    for (int s = 0; s < STAGES - 1; s++) issue(s, s);

    for (int kb = 0; kb < nk; kb++) {
        cp_wait();
        __syncthreads();   // single barrier per K-tile (3-stage rotation)

        if (kb + STAGES - 1 < nk) issue(kb + STAGES - 1, (kb + STAGES - 1) % STAGES);
        else                      cp_commit();   // keep group counts aligned

        const uint32_t* Au = As + (kb % STAGES) * ASTAGE;
        const uint32_t* Bu = Bs + (kb % STAGES) * BSTAGE;

        #pragma unroll
        for (int s = 0; s < 2; s++) {        // two k16 steps
            uint32_t afr[4][4], bfr[8][2];
            #pragma unroll
            for (int mt = 0; mt < 4; mt++) {
                int r = mb + mt * 16 + qr;
                afr[mt][0] = Au[r * RSTR + 8 * s + qc];
                afr[mt][1] = Au[(r + 8) * RSTR + 8 * s + qc];
                afr[mt][2] = Au[r * RSTR + 8 * s + qc + 4];
                afr[mt][3] = Au[(r + 8) * RSTR + 8 * s + qc + 4];
            }
            #pragma unroll
            for (int nt = 0; nt < 8; nt++) {
                int n = nb + nt * 8 + qr;
                bfr[nt][0] = Bu[(8 * s + qc) * BSTR + n];
                bfr[nt][1] = Bu[(8 * s + qc + 4) * BSTR + n];
            }
            #pragma unroll
            for (int mt = 0; mt < 4; mt++)
                #pragma unroll
                for (int nt = 0; nt < 8; nt++)
                    mma_f16(acc[mt][nt], afr[mt], bfr[nt]);
        }
    }

    // -------- epilogue --------
    #pragma unroll
    for (int mt = 0; mt < 4; mt++) {
        int rl0 = mb + mt * 16 + qr;
        int rl1 = rl0 + 8;
        if (MODE == 0) {
            int r0 = m0 + rl0, r1 = m0 + rl1;
            #pragma unroll
            for (int nt = 0; nt < 8; nt++) {
                int c = n0 + nb + nt * 8 + qc * 2;
                float v0 = fmaxf(acc[mt][nt][0], 0.f); v0 *= v0;
                float v1 = fmaxf(acc[mt][nt][1], 0.f); v1 *= v1;
                float v2 = fmaxf(acc[mt][nt][2], 0.f); v2 *= v2;
                float v3 = fmaxf(acc[mt][nt][3], 0.f); v3 *= v3;
                *(__half2*)&g_s1h[(size_t)r0 * Nn + c] = __floats2half2_rn(v0, v1);
                *(__half2*)&g_s1h[(size_t)r1 * Nn + c] = __floats2half2_rn(v2, v3);
            }
        } else if (MODE == 1) {
            int r0 = m0 + rl0, r1 = m0 + rl1;
            #pragma unroll
            for (int nt = 0; nt < 8; nt++) {
                int c = n0 + nb + nt * 8 + qc * 2;
                *(float2*)&Cglob[(size_t)r0 * Nn + c] = make_float2(acc[mt][nt][0], acc[mt][nt][1]);
                *(float2*)&Cglob[(size_t)r1 * Nn + c] = make_float2(acc[mt][nt][2], acc[mt][nt][3]);
            }
        } else if (MODE == 2) {
            bool va = (m0 + rl0) < ne, vb = (m0 + rl1) < ne;
            int tk0 = va ? g_tok[e * Tt + m0 + rl0] : 0;
            int tk1 = vb ? g_tok[e * Tt + m0 + rl1] : 0;
            float w0 = va ? g_combine[tk0 * Ee + e] : 0.f;
            float w1 = vb ? g_combine[tk1 * Ee + e] : 0.f;
            size_t cr0 = (size_t)(off_e + m0 + rl0) * DF;
            size_t cr1 = (size_t)(off_e + m0 + rl1) * DF;
            #pragma unroll
            for (int nt = 0; nt < 8; nt++) {
                int c = n0 + nb + nt * 8 + qc * 2;
                float v0 = fmaxf(acc[mt][nt][0], 0.f); v0 = v0 * v0 * w0;
                float v1 = fmaxf(acc[mt][nt][1], 0.f); v1 = v1 * v1 * w0;
                float v2 = fmaxf(acc[mt][nt][2], 0.f); v2 = v2 * v2 * w1;
                float v3 = fmaxf(acc[mt][nt][3], 0.f); v3 = v3 * v3 * w1;
                if (va) *(__half2*)&g_acth[cr0 + c] = __floats2half2_rn(v0, v1);
                if (vb) *(__half2*)&g_acth[cr1 + c] = __floats2half2_rn(v2, v3);
            }
        } else {  // MODE 3: vector atomic scatter into out
            bool va = (m0 + rl0) < ne, vb = (m0 + rl1) < ne;
            int tk0 = va ? g_tok[e * Tt + m0 + rl0] : 0;
            int tk1 = vb ? g_tok[e * Tt + m0 + rl1] : 0;
            #pragma unroll
            for (int nt = 0; nt < 8; nt++) {
                int c = n0 + nb + nt * 8 + qc * 2;
                if (va) red2(&Cglob[(size_t)tk0 * Hd + c], acc[mt][nt][0], acc[mt][nt][1]);
                if (vb) red2(&Cglob[(size_t)tk1 * Hd + c], acc[mt][nt][2], acc[mt][nt][3]);
            }
        }
    }
}

// ---------------- launch ----------------
extern "C" void kernel_launch(void* const* d_in, const int* in_sizes, int n_in,
                              void* d_out, int out_size) {
    const float* x     = (const float*)d_in[0];
    const float* rw    = (const float*)d_in[1];
    const float* rb    = (const float*)d_in[2];
    const float* w_up  = (const float*)d_in[3];
    const float* w_dn  = (const float*)d_in[4];
    const float* s_up  = (const float*)d_in[5];
    const float* s_dn  = (const float*)d_in[6];
    float* out = (float*)d_out;

    cudaFuncSetAttribute(gemm_kernel<0>, cudaFuncAttributeMaxDynamicSharedMemorySize, SMEM_BYTES);
    cudaFuncSetAttribute(gemm_kernel<1>, cudaFuncAttributeMaxDynamicSharedMemorySize, SMEM_BYTES);
    cudaFuncSetAttribute(gemm_kernel<2>, cudaFuncAttributeMaxDynamicSharedMemorySize, SMEM_BYTES);
    cudaFuncSetAttribute(gemm_kernel<3>, cudaFuncAttributeMaxDynamicSharedMemorySize, SMEM_BYTES);

    uint32_t *wupp, *wdnp, *supp, *sdnp;
    cudaGetSymbolAddress((void**)&wupp, g_wupp);
    cudaGetSymbolAddress((void**)&wdnp, g_wdnp);
    cudaGetSymbolAddress((void**)&supp, g_supp);
    cudaGetSymbolAddress((void**)&sdnp, g_sdnp);

    // pre-pass: x -> fp16; weights -> k-pair-packed fp16 (streaming, layout preserved)
    cvt_x_kernel<<<(Tt * Hd / 4) / 256, 256>>>(x);
    pack_kernel<<<(int)(((size_t)Ee * (Hd / 2) * (DF / 4)) / 256), 256>>>(w_up, wupp, DF, 8);
    pack_kernel<<<(int)(((size_t)Ee * (DF / 2) * (Hd / 4)) / 256), 256>>>(w_dn, wdnp, Hd, 9);
    pack_kernel<<<(int)(((size_t)(Hd / 2) * (DS / 4)) / 256), 256>>>(s_up, supp, DS, 10);
    pack_kernel<<<(int)(((size_t)(DS / 2) * (Hd / 4)) / 256), 256>>>(s_dn, sdnp, Hd, 9);

    zero_cnt_kernel<<<1, 32>>>();
    router_kernel<<<Tt, 128>>>(x, rw, rb);
    offs_kernel<<<1, 32>>>();

    // routed up: per-expert gathered GEMM -> g_acth
    gemm_kernel<2><<<dim3(DF / BN, Tt / BM, Ee), NTHR, SMEM_BYTES>>>(nullptr);

    // shared expert
    gemm_kernel<0><<<dim3(DS / BN, Tt / BM, 1), NTHR, SMEM_BYTES>>>(nullptr);
    gemm_kernel<1><<<dim3(Hd / BN, Tt / BM, 1), NTHR, SMEM_BYTES>>>(out);

    // routed down: atomic scatter onto out (after shared wrote it)
    gemm_kernel<3><<<dim3(Hd / BN, Tt / BM, Ee), NTHR, SMEM_BYTES>>>(out);
}